// round 14
// baseline (speedup 1.0000x reference)
#include <cuda_runtime.h>
#include <cuda_fp16.h>

// Problem constants (fixed by dataset)
#define NN   50000      // nodes
#define INF_ 128        // input features
#define CC   256        // H*HID = 4*64
#define EE   800000     // edges (without self loops)
#define ET   850000     // edges + self loops
#define NSCAN_BLK 196   // ceil(50000/256)
#define GMX  391        // ceil(NN/128): gemm grid x; also hist role blocks

// ---------------- scratch (static device globals; POD only) -----------------
// g_deg/g_cnt/g_bnsum/g_bnsq must be ZERO at entry. First call: .bss zeroing;
// every execution re-zeroes them in k_agg2's tail so graph replays start clean.
__device__ unsigned g_h1h[NN * (CC / 2)]; // layer-1 features, half2 bit-patterns
__device__ float  g_out1[NN * CC];        // layer-1 aggregated output
__device__ float4 g_es1[NN];
__device__ float4 g_ed1[NN];
__device__ int    g_deg[NN];
__device__ int    g_incl[NN];
__device__ int    g_rowptr[NN + 1];
__device__ int    g_cnt[NN];
__device__ int    g_bsums[256];
__device__ int2   g_sed[ET];              // packed (src, edge-id)
__device__ float  g_bnsum[CC], g_bnsq[CC];
__device__ float2 g_h2[NN];
__device__ float  g_es2[NN], g_ed2[NN];
__device__ int    g_is64;             // edge_index dtype flag (set in gemm1's hist role)

__device__ __forceinline__ float lrelu(float x) { return x > 0.f ? x : 0.2f * x; }

__device__ __forceinline__ unsigned h2bits(float a, float b) {
    __half2 h = __floats2half2_rn(a, b);
    return *(unsigned*)&h;
}
__device__ __forceinline__ void bits2f(unsigned u, float& lo, float& hi) {
    __half2 h = *(__half2*)&u;
    lo = __low2float(h);
    hi = __high2float(h);
}

// ---------------- CSR scans ----------------
__global__ void k_scan1() {
    __shared__ int s[256];
    int t = threadIdx.x;
    int i = blockIdx.x * 256 + t;
    int v = (i < NN) ? g_deg[i] : 0;
    s[t] = v;
    __syncthreads();
    for (int off = 1; off < 256; off <<= 1) {
        int tv = (t >= off) ? s[t - off] : 0;
        __syncthreads();
        s[t] += tv;
        __syncthreads();
    }
    if (i < NN) g_incl[i] = s[t];
    if (t == 255) g_bsums[blockIdx.x] = s[255];
}

// scan3 with inline block-prefix of bsums
__global__ void k_scan3() {
    __shared__ int sp[256];
    int t = threadIdx.x;
    int v = (t < blockIdx.x) ? g_bsums[t] : 0;   // blockIdx.x <= 195 < 256
    sp[t] = v;
    __syncthreads();
#pragma unroll
    for (int off = 128; off; off >>= 1) {
        if (t < off) sp[t] += sp[t + off];
        __syncthreads();
    }
    int prefix = sp[0];
    int i = blockIdx.x * 256 + t;
    if (i < NN) g_rowptr[i + 1] = prefix + g_incl[i];
    if (i == 0) g_rowptr[0] = 0;
}

__global__ void k_scatter(const int* __restrict__ w) {
    int i = blockIdx.x * 256 + threadIdx.x;
    if (i >= ET) return;
    int s, d;
    if (i < EE) {
        if (g_is64) {
            s = (int)((const long long*)w)[i];
            d = (int)((const long long*)w)[EE + i];
        } else {
            s = w[i];
            d = w[EE + i];
        }
    } else {
        s = d = i - EE;
    }
    int pos = g_rowptr[d] + atomicAdd(&g_cnt[d], 1);
    g_sed[pos] = make_int2(s, i);    // single 8B store
}

// ------ GEMM1 (1xTF32, double-buffered) + fused es/ed logits + HIST role ---
#define GM 128
#define GN 64
#define GK 16
#define NKT (INF_ / GK)   // 8 K-tiles
#define ASTR 20     // A smem k-stride (words)
#define BSTR 72     // B smem n-stride (words)

__device__ __forceinline__ unsigned tf32_of(float x) {
    unsigned r;
    asm("cvt.rna.tf32.f32 %0, %1;" : "=r"(r) : "f"(x));
    return r;
}
__device__ __forceinline__ void mma_tf32(float* c, const unsigned* a,
                                         unsigned b0, unsigned b1) {
    asm volatile(
        "mma.sync.aligned.m16n8k8.row.col.f32.tf32.tf32.f32 "
        "{%0,%1,%2,%3}, {%4,%5,%6,%7}, {%8,%9}, {%0,%1,%2,%3};"
        : "+f"(c[0]), "+f"(c[1]), "+f"(c[2]), "+f"(c[3])
        : "r"(a[0]), "r"(a[1]), "r"(a[2]), "r"(a[3]), "r"(b0), "r"(b1));
}

__global__ __launch_bounds__(256) void k_gemm1(const float* __restrict__ A,
                                               const float* __restrict__ B,
                                               const float* __restrict__ as1,
                                               const float* __restrict__ ad1,
                                               const int* __restrict__ ew) {
    // ---- role: blockIdx.y == 4 -> edge histogram (overlapped with GEMM) ----
    if (blockIdx.y == 4) {
        __shared__ int s64;
        if (threadIdx.x == 0) {
            int is64 = 1;
#pragma unroll 1
            for (int k = 1; k < 129; k += 2)
                if (ew[k] != 0) { is64 = 0; break; }
            s64 = is64;
            if (blockIdx.x == 0) g_is64 = is64;
        }
        __syncthreads();
        int is64 = s64;
        const long long* ll = (const long long*)ew;
        int stride = GMX * 256;
        for (int i = blockIdx.x * 256 + threadIdx.x; i < ET; i += stride) {
            int d = (i < EE) ? (is64 ? (int)ll[EE + i] : ew[EE + i]) : (i - EE);
            atomicAdd(&g_deg[d], 1);
        }
        return;
    }

    __shared__ unsigned Ah[2][GM * ASTR];
    __shared__ unsigned Bh[2][GK * BSTR];
    __shared__ float s_es[GM], s_ed[GM];
    int tid = threadIdx.x;
    int bm = blockIdx.x * GM;
    int head = blockIdx.y;          // GN == dh == 64: one head per y-block
    int bn = head * GN;
    int wid = tid >> 5, lane = tid & 31;
    int wm = wid & 3, wn = wid >> 2;          // 4x2 warp grid, warp tile 32x32
    int g = lane >> 2, tg = lane & 3;

    // per-thread load coordinates (fixed across tiles)
    int ar0 = tid >> 2, akc0 = (tid & 3) * 4;          // A piece 0
    int ar1 = (tid + 256) >> 2, akc1 = ((tid + 256) & 3) * 4;  // A piece 1
    int bkk = tid >> 4, bnc = (tid & 15) * 4;

    float acc[2][4][4];
#pragma unroll
    for (int mi = 0; mi < 2; mi++)
#pragma unroll
        for (int ni = 0; ni < 4; ni++)
#pragma unroll
            for (int c = 0; c < 4; c++) acc[mi][ni][c] = 0.f;

    float4 a0v, a1v, bv;
    // fetch tile 0
    {
        a0v = make_float4(0.f, 0.f, 0.f, 0.f);
        a1v = make_float4(0.f, 0.f, 0.f, 0.f);
        if (bm + ar0 < NN) a0v = *(const float4*)&A[(size_t)(bm + ar0) * INF_ + akc0];
        if (bm + ar1 < NN) a1v = *(const float4*)&A[(size_t)(bm + ar1) * INF_ + akc1];
        bv = *(const float4*)&B[(size_t)bkk * CC + bn + bnc];
    }
    // store tile 0 -> buf 0
    {
        int base0 = ar0 * ASTR + akc0;
        Ah[0][base0] = tf32_of(a0v.x); Ah[0][base0 + 1] = tf32_of(a0v.y);
        Ah[0][base0 + 2] = tf32_of(a0v.z); Ah[0][base0 + 3] = tf32_of(a0v.w);
        int base1 = ar1 * ASTR + akc1;
        Ah[0][base1] = tf32_of(a1v.x); Ah[0][base1 + 1] = tf32_of(a1v.y);
        Ah[0][base1 + 2] = tf32_of(a1v.z); Ah[0][base1 + 3] = tf32_of(a1v.w);
        int bbase = bkk * BSTR + bnc;
        Bh[0][bbase] = tf32_of(bv.x); Bh[0][bbase + 1] = tf32_of(bv.y);
        Bh[0][bbase + 2] = tf32_of(bv.z); Bh[0][bbase + 3] = tf32_of(bv.w);
    }
    __syncthreads();

    int cur = 0;
#pragma unroll
    for (int kt = 0; kt < NKT; kt++) {
        // prefetch next tile into registers
        if (kt + 1 < NKT) {
            int k0 = (kt + 1) * GK;
            a0v = make_float4(0.f, 0.f, 0.f, 0.f);
            a1v = make_float4(0.f, 0.f, 0.f, 0.f);
            if (bm + ar0 < NN) a0v = *(const float4*)&A[(size_t)(bm + ar0) * INF_ + k0 + akc0];
            if (bm + ar1 < NN) a1v = *(const float4*)&A[(size_t)(bm + ar1) * INF_ + k0 + akc1];
            bv = *(const float4*)&B[(size_t)(k0 + bkk) * CC + bn + bnc];
        }
        // compute on buf[cur]
        const unsigned* Ac = Ah[cur];
        const unsigned* Bc = Bh[cur];
#pragma unroll
        for (int ks = 0; ks < 2; ks++) {
            int kb = ks * 8;
            unsigned ah[2][4];
#pragma unroll
            for (int mi = 0; mi < 2; mi++) {
                int R = wm * 32 + mi * 16;
                int b0 = (R + g) * ASTR + kb + tg;
                int b1 = (R + 8 + g) * ASTR + kb + tg;
                ah[mi][0] = Ac[b0]; ah[mi][1] = Ac[b1];
                ah[mi][2] = Ac[b0 + 4]; ah[mi][3] = Ac[b1 + 4];
            }
#pragma unroll
            for (int ni = 0; ni < 4; ni++) {
                int C = wn * 32 + ni * 8;
                unsigned bh0 = Bc[(kb + tg) * BSTR + C + g];
                unsigned bh1 = Bc[(kb + 4 + tg) * BSTR + C + g];
#pragma unroll
                for (int mi = 0; mi < 2; mi++)
                    mma_tf32(acc[mi][ni], ah[mi], bh0, bh1);
            }
        }
        // store prefetched tile into the other buffer
        if (kt + 1 < NKT) {
            int nxt = cur ^ 1;
            int base0 = ar0 * ASTR + akc0;
            Ah[nxt][base0] = tf32_of(a0v.x); Ah[nxt][base0 + 1] = tf32_of(a0v.y);
            Ah[nxt][base0 + 2] = tf32_of(a0v.z); Ah[nxt][base0 + 3] = tf32_of(a0v.w);
            int base1 = ar1 * ASTR + akc1;
            Ah[nxt][base1] = tf32_of(a1v.x); Ah[nxt][base1 + 1] = tf32_of(a1v.y);
            Ah[nxt][base1 + 2] = tf32_of(a1v.z); Ah[nxt][base1 + 3] = tf32_of(a1v.w);
            int bbase = bkk * BSTR + bnc;
            Bh[nxt][bbase] = tf32_of(bv.x); Bh[nxt][bbase + 1] = tf32_of(bv.y);
            Bh[nxt][bbase + 2] = tf32_of(bv.z); Bh[nxt][bbase + 3] = tf32_of(bv.w);
            __syncthreads();
            cur = nxt;
        }
    }

    // epilogue 1: fp16 h1 store
#pragma unroll
    for (int mi = 0; mi < 2; mi++) {
        int row0 = bm + wm * 32 + mi * 16 + g;
#pragma unroll
        for (int ni = 0; ni < 4; ni++) {
            int col = bn + wn * 32 + ni * 8 + 2 * tg;   // even
            if (row0 < NN)
                g_h1h[(size_t)row0 * (CC / 2) + (col >> 1)] =
                    h2bits(acc[mi][ni][0], acc[mi][ni][1]);
            if (row0 + 8 < NN)
                g_h1h[(size_t)(row0 + 8) * (CC / 2) + (col >> 1)] =
                    h2bits(acc[mi][ni][2], acc[mi][ni][3]);
        }
    }

    // epilogue 2: per-row es/ed dot over this head's 64 channels
    const float* asv = as1 + head * GN;
    const float* adv = ad1 + head * GN;
    float ps[2][2] = {{0, 0}, {0, 0}};   // [mi][row0 / row0+8]
    float pd[2][2] = {{0, 0}, {0, 0}};
#pragma unroll
    for (int ni = 0; ni < 4; ni++) {
        int c = wn * 32 + ni * 8 + 2 * tg;   // local col within head
        float a0 = asv[c], a1 = asv[c + 1];
        float d0 = adv[c], d1 = adv[c + 1];
#pragma unroll
        for (int mi = 0; mi < 2; mi++) {
            ps[mi][0] += acc[mi][ni][0] * a0 + acc[mi][ni][1] * a1;
            pd[mi][0] += acc[mi][ni][0] * d0 + acc[mi][ni][1] * d1;
            ps[mi][1] += acc[mi][ni][2] * a0 + acc[mi][ni][3] * a1;
            pd[mi][1] += acc[mi][ni][2] * d0 + acc[mi][ni][3] * d1;
        }
    }
#pragma unroll
    for (int off = 1; off <= 2; off <<= 1) {
#pragma unroll
        for (int mi = 0; mi < 2; mi++)
#pragma unroll
            for (int rr = 0; rr < 2; rr++) {
                ps[mi][rr] += __shfl_xor_sync(0xffffffffu, ps[mi][rr], off);
                pd[mi][rr] += __shfl_xor_sync(0xffffffffu, pd[mi][rr], off);
            }
    }
    if (wn == 1 && tg == 0) {
#pragma unroll
        for (int mi = 0; mi < 2; mi++)
#pragma unroll
            for (int rr = 0; rr < 2; rr++) {
                int R = wm * 32 + mi * 16 + rr * 8 + g;
                s_es[R] = ps[mi][rr];
                s_ed[R] = pd[mi][rr];
            }
    }
    __syncthreads();
    if (wn == 0 && tg == 0) {
#pragma unroll
        for (int mi = 0; mi < 2; mi++)
#pragma unroll
            for (int rr = 0; rr < 2; rr++) {
                int R = wm * 32 + mi * 16 + rr * 8 + g;
                int row = bm + R;
                if (row < NN) {
                    ((float*)&g_es1[row])[head] = ps[mi][rr] + s_es[R];
                    ((float*)&g_ed1[row])[head] = pd[mi][rr] + s_ed[R];
                }
            }
    }
}

// ------- layer-1 softmax + aggregation: TWO warps per node (channel split) --
// warp half=0 -> channels 0..127 (heads 0,1); half=1 -> 128..255 (heads 2,3).
// Per lane: 4 channels = one uint2 of half2. Per edge: 2 exps, uint2 gather.
__device__ __forceinline__ void agg_edge2(float2 ev, uint2 hv, float2 edn, int lane,
                                          float* acc, float& dlo, float& dhi) {
    float plo = __expf(lrelu(ev.x + edn.x));
    float phi = __expf(lrelu(ev.y + edn.y));
    dlo += plo; dhi += phi;
    float pv = lane < 16 ? plo : phi;
    float e0, e1, e2, e3;
    bits2f(hv.x, e0, e1); bits2f(hv.y, e2, e3);
    acc[0] = fmaf(pv, e0, acc[0]); acc[1] = fmaf(pv, e1, acc[1]);
    acc[2] = fmaf(pv, e2, acc[2]); acc[3] = fmaf(pv, e3, acc[3]);
}

__global__ __launch_bounds__(256) void k_agg1() {
    __shared__ float bnP[2][4][CC];   // [sum/sq][node-slot][channel], 8KB
    int tid = threadIdx.x;
    int wid = tid >> 5;
    int lane = tid & 31;
    int n = (blockIdx.x << 2) + (wid >> 1);  // NN = 12500 blocks * 4 nodes
    int half = wid & 1;
    int r0 = g_rowptr[n], r1 = g_rowptr[n + 1];
    float2 edn = ((const float2*)&g_ed1[n])[half];
    // channel base for this lane: half*128 + 4*lane ; g_h1h offset = half*64 + 2*lane
    const unsigned* hb = g_h1h + half * 64 + 2 * lane;
    float acc[4] = {0, 0, 0, 0};
    float dlo = 0.f, dhi = 0.f;
    int j = r0;
    for (; j + 3 < r1; j += 4) {
        int s0 = g_sed[j].x, s1 = g_sed[j + 1].x, s2 = g_sed[j + 2].x, s3 = g_sed[j + 3].x;
        float2 e0 = ((const float2*)&g_es1[s0])[half];
        float2 e1 = ((const float2*)&g_es1[s1])[half];
        float2 e2 = ((const float2*)&g_es1[s2])[half];
        float2 e3 = ((const float2*)&g_es1[s3])[half];
        uint2 h0 = *(const uint2*)(hb + (size_t)s0 * (CC / 2));
        uint2 h1 = *(const uint2*)(hb + (size_t)s1 * (CC / 2));
        uint2 h2 = *(const uint2*)(hb + (size_t)s2 * (CC / 2));
        uint2 h3 = *(const uint2*)(hb + (size_t)s3 * (CC / 2));
        agg_edge2(e0, h0, edn, lane, acc, dlo, dhi);
        agg_edge2(e1, h1, edn, lane, acc, dlo, dhi);
        agg_edge2(e2, h2, edn, lane, acc, dlo, dhi);
        agg_edge2(e3, h3, edn, lane, acc, dlo, dhi);
    }
    for (; j < r1; j++) {
        int s0 = g_sed[j].x;
        float2 e0 = ((const float2*)&g_es1[s0])[half];
        uint2 h0 = *(const uint2*)(hb + (size_t)s0 * (CC / 2));
        agg_edge2(e0, h0, edn, lane, acc, dlo, dhi);
    }
    // dlo/dhi complete in every lane (per-head denominators): NO reduction.
    float invlo = 1.f / (dlo + 1e-16f);
    float invhi = 1.f / (dhi + 1e-16f);
    float invv = lane < 16 ? invlo : invhi;
    float o0 = acc[0] * invv, o1 = acc[1] * invv;
    float o2 = acc[2] * invv, o3 = acc[3] * invv;
    // store: float4 index = (half*128 + 4*lane)/4 = half*32 + lane
    ((float4*)&g_out1[(size_t)n * CC])[half * 32 + lane] = make_float4(o0, o1, o2, o3);
    // BN partials: slot = node-in-block; warps (2k,2k+1) fill disjoint halves
    {
        int slot = wid >> 1;
        int cb = half * 128 + 4 * lane;
        *(float4*)&bnP[0][slot][cb] = make_float4(o0, o1, o2, o3);
        *(float4*)&bnP[1][slot][cb] = make_float4(o0 * o0, o1 * o1, o2 * o2, o3 * o3);
    }
    __syncthreads();
    float s = 0.f, q = 0.f;
#pragma unroll
    for (int k = 0; k < 4; k++) {
        s += bnP[0][k][tid];
        q += bnP[1][k][tid];
    }
    atomicAdd(&g_bnsum[tid], s);
    atomicAdd(&g_bnsq[tid], q);
}

// --- fused BN-finalize + BN-apply + ELU + GEMM2 + layer-2 logits ------------
__global__ __launch_bounds__(256) void k_l2pre(const float* __restrict__ gamma,
                                               const float* __restrict__ beta,
                                               const float* __restrict__ W2,
                                               const float* __restrict__ as2,
                                               const float* __restrict__ ad2) {
    __shared__ float s_sc[CC], s_sh[CC];
    int tid = threadIdx.x;
    {
        float mean = g_bnsum[tid] * (1.f / NN);
        float var = g_bnsq[tid] * (1.f / NN) - mean * mean;
        if (var < 0.f) var = 0.f;
        float sc = gamma[tid] * rsqrtf(var + 1e-5f);
        s_sc[tid] = sc;
        s_sh[tid] = beta[tid] - mean * sc;
    }
    __syncthreads();
    int n = (blockIdx.x << 3) + (tid >> 5);
    int lane = tid & 31;
    const float4* orow = (const float4*)&g_out1[(size_t)n * CC];
    const float4* sc4 = (const float4*)s_sc;
    const float4* sh4 = (const float4*)s_sh;
    const float2* W2v = (const float2*)W2;   // [256] of (w0,w1)
    float a0 = 0.f, a1 = 0.f;
#pragma unroll
    for (int half = 0; half < 2; half++) {
        int idx = half * 32 + lane;
        float4 ov = orow[idx];
        float4 sc = sc4[idx];
        float4 sh = sh4[idx];
        float v[4] = {ov.x * sc.x + sh.x, ov.y * sc.y + sh.y,
                      ov.z * sc.z + sh.z, ov.w * sc.w + sh.w};
#pragma unroll
        for (int i = 0; i < 4; i++) {
            float vv = v[i] > 0.f ? v[i] : expm1f(v[i]);
            float2 w = W2v[idx * 4 + i];
            a0 = fmaf(vv, w.x, a0);
            a1 = fmaf(vv, w.y, a1);
        }
    }
#pragma unroll
    for (int off = 16; off; off >>= 1) {
        a0 += __shfl_xor_sync(0xffffffffu, a0, off);
        a1 += __shfl_xor_sync(0xffffffffu, a1, off);
    }
    if (lane == 0) {
        g_h2[n] = make_float2(a0, a1);
        g_es2[n] = a0 * as2[0] + a1 * as2[1];
        g_ed2[n] = a0 * ad2[0] + a1 * ad2[1];
    }
}

// --- layer-2 softmax + aggregation + att output + scratch re-zero -----------
__global__ void k_agg2(const float* __restrict__ bias2, float* __restrict__ out) {
    // re-zero scratch for the NEXT graph replay (independent addresses)
    {
        int gid = blockIdx.x * 256 + threadIdx.x;
        if (gid < NN) { g_deg[gid] = 0; g_cnt[gid] = 0; }
        if (gid < CC) { g_bnsum[gid] = 0.f; g_bnsq[gid] = 0.f; }
    }
    int n = (blockIdx.x * 256 + threadIdx.x) >> 5;
    int lane = threadIdx.x & 31;
    if (n >= NN) return;
    int r0 = g_rowptr[n], r1 = g_rowptr[n + 1];
    float edn = g_ed2[n];
    float den = 0.f, a0 = 0.f, a1 = 0.f;
    for (int j = r0 + lane; j < r1; j += 32) {
        int s = g_sed[j].x;
        float p = __expf(lrelu(g_es2[s] + edn));
        den += p;
        float2 h = g_h2[s];
        a0 = fmaf(p, h.x, a0);
        a1 = fmaf(p, h.y, a1);
    }
#pragma unroll
    for (int off = 16; off; off >>= 1) {
        den += __shfl_xor_sync(0xffffffffu, den, off);
        a0  += __shfl_xor_sync(0xffffffffu, a0, off);
        a1  += __shfl_xor_sync(0xffffffffu, a1, off);
    }
    float inv = 1.f / (den + 1e-16f);
    for (int j = r0 + lane; j < r1; j += 32) {
        int2 se = g_sed[j];
        float p = __expf(lrelu(g_es2[se.x] + edn));
        out[2 * NN + se.y] = p * inv;
    }
    if (lane == 0) {
        out[2 * n]     = a0 * inv + bias2[0];
        out[2 * n + 1] = a1 * inv + bias2[1];
    }
}

// ---------------- launch (single stream) ----------------
extern "C" void kernel_launch(void* const* d_in, const int* in_sizes, int n_in,
                              void* d_out, int out_size) {
    const float* x     = (const float*)d_in[0];
    const int*   ei    = (const int*)d_in[1];     // int32 or int64, autodetected
    const float* W1    = (const float*)d_in[2];
    const float* as1   = (const float*)d_in[3];
    const float* ad1   = (const float*)d_in[4];
    // d_in[5] = bias1 (cancels under batch-norm; skipped)
    const float* gamma = (const float*)d_in[6];
    const float* beta  = (const float*)d_in[7];
    const float* W2    = (const float*)d_in[8];
    const float* as2   = (const float*)d_in[9];
    const float* ad2   = (const float*)d_in[10];
    const float* bias2 = (const float*)d_in[11];
    float*       out   = (float*)d_out;

    // GEMM1 + es/ed epilogue + HIST role (y==4) in one launch
    dim3 ggrid(GMX, 5);
    k_gemm1<<<ggrid, 256>>>(x, W1, as1, ad1, ei);

    // CSR scans + scatter (deg produced by gemm1's hist role)
    k_scan1<<<NSCAN_BLK, 256>>>();
    k_scan3<<<NSCAN_BLK, 256>>>();
    k_scatter<<<(ET + 255) / 256, 256>>>(ei);

    // layer-1 aggregation: 2 warps per node -> NN/4 nodes per 256-thread block
    k_agg1<<<NN / 4, 256>>>();

    // layer 2 (BN finalize fused into l2pre)
    int wgrid = (NN + 7) / 8;
    k_l2pre<<<wgrid, 256>>>(gamma, beta, W2, as2, ad2);
    k_agg2<<<wgrid, 256>>>(bias2, out);
}

// round 15
// speedup vs baseline: 1.2262x; 1.2262x over previous
#include <cuda_runtime.h>
#include <cuda_fp16.h>

// Problem constants (fixed by dataset)
#define NN   50000      // nodes
#define INF_ 128        // input features
#define CC   256        // H*HID = 4*64
#define EE   800000     // edges (without self loops)
#define ET   850000     // edges + self loops
#define NSCAN_BLK 196   // ceil(50000/256)
#define GMX  391        // ceil(NN/128): gemm grid x; also hist role blocks

// ---------------- scratch (static device globals; POD only) -----------------
// g_deg/g_cnt/g_bnsum/g_bnsq must be ZERO at entry. First call: .bss zeroing;
// every execution re-zeroes them in k_agg2's tail so graph replays start clean.
__device__ unsigned g_h1h[NN * (CC / 2)]; // layer-1 features, half2 bit-patterns
__device__ float  g_out1[NN * CC];        // layer-1 aggregated output
__device__ float4 g_es1[NN];
__device__ float4 g_ed1[NN];
__device__ int    g_deg[NN];
__device__ int    g_incl[NN];
__device__ int    g_rowptr[NN + 1];
__device__ int    g_cnt[NN];
__device__ int    g_bsums[256];
__device__ int2   g_sed[ET];              // packed (src, edge-id)
__device__ float  g_bnsum[CC], g_bnsq[CC];
__device__ float2 g_h2[NN];
__device__ float  g_es2[NN], g_ed2[NN];
__device__ int    g_is64;             // edge_index dtype flag (set in gemm1's hist role)

__device__ __forceinline__ float lrelu(float x) { return x > 0.f ? x : 0.2f * x; }

__device__ __forceinline__ unsigned h2bits(float a, float b) {
    __half2 h = __floats2half2_rn(a, b);
    return *(unsigned*)&h;
}
__device__ __forceinline__ void bits2f(unsigned u, float& lo, float& hi) {
    __half2 h = *(__half2*)&u;
    lo = __low2float(h);
    hi = __high2float(h);
}

// ---------------- CSR scans ----------------
__global__ void k_scan1() {
    __shared__ int s[256];
    int t = threadIdx.x;
    int i = blockIdx.x * 256 + t;
    int v = (i < NN) ? g_deg[i] : 0;
    s[t] = v;
    __syncthreads();
    for (int off = 1; off < 256; off <<= 1) {
        int tv = (t >= off) ? s[t - off] : 0;
        __syncthreads();
        s[t] += tv;
        __syncthreads();
    }
    if (i < NN) g_incl[i] = s[t];
    if (t == 255) g_bsums[blockIdx.x] = s[255];
}

// scan3 with inline block-prefix of bsums
__global__ void k_scan3() {
    __shared__ int sp[256];
    int t = threadIdx.x;
    int v = (t < blockIdx.x) ? g_bsums[t] : 0;   // blockIdx.x <= 195 < 256
    sp[t] = v;
    __syncthreads();
#pragma unroll
    for (int off = 128; off; off >>= 1) {
        if (t < off) sp[t] += sp[t + off];
        __syncthreads();
    }
    int prefix = sp[0];
    int i = blockIdx.x * 256 + t;
    if (i < NN) g_rowptr[i + 1] = prefix + g_incl[i];
    if (i == 0) g_rowptr[0] = 0;
}

// scatter: 2 edges per thread for MLP
__global__ void k_scatter(const int* __restrict__ w) {
    int base = (blockIdx.x * 256 + threadIdx.x) * 2;
    if (base >= ET) return;
    int is64 = g_is64;
    const long long* ll = (const long long*)w;
    int s0, d0, s1 = 0, d1 = 0;
    bool has1 = (base + 1 < ET);
    {
        int i = base;
        if (i < EE) {
            if (is64) { s0 = (int)ll[i]; d0 = (int)ll[EE + i]; }
            else      { s0 = w[i];       d0 = w[EE + i]; }
        } else { s0 = d0 = i - EE; }
    }
    if (has1) {
        int i = base + 1;
        if (i < EE) {
            if (is64) { s1 = (int)ll[i]; d1 = (int)ll[EE + i]; }
            else      { s1 = w[i];       d1 = w[EE + i]; }
        } else { s1 = d1 = i - EE; }
    }
    int r0 = g_rowptr[d0];
    int r1 = has1 ? g_rowptr[d1] : 0;
    int p0 = r0 + atomicAdd(&g_cnt[d0], 1);
    g_sed[p0] = make_int2(s0, base);
    if (has1) {
        int p1 = r1 + atomicAdd(&g_cnt[d1], 1);
        g_sed[p1] = make_int2(s1, base + 1);
    }
}

// ------ GEMM1 (1xTF32, double-buffered) + fused es/ed logits + HIST role ---
#define GM 128
#define GN 64
#define GK 16
#define NKT (INF_ / GK)   // 8 K-tiles
#define ASTR 20     // A smem k-stride (words)
#define BSTR 72     // B smem n-stride (words)

__device__ __forceinline__ unsigned tf32_of(float x) {
    unsigned r;
    asm("cvt.rna.tf32.f32 %0, %1;" : "=r"(r) : "f"(x));
    return r;
}
__device__ __forceinline__ void mma_tf32(float* c, const unsigned* a,
                                         unsigned b0, unsigned b1) {
    asm volatile(
        "mma.sync.aligned.m16n8k8.row.col.f32.tf32.tf32.f32 "
        "{%0,%1,%2,%3}, {%4,%5,%6,%7}, {%8,%9}, {%0,%1,%2,%3};"
        : "+f"(c[0]), "+f"(c[1]), "+f"(c[2]), "+f"(c[3])
        : "r"(a[0]), "r"(a[1]), "r"(a[2]), "r"(a[3]), "r"(b0), "r"(b1));
}

__global__ __launch_bounds__(256) void k_gemm1(const float* __restrict__ A,
                                               const float* __restrict__ B,
                                               const float* __restrict__ as1,
                                               const float* __restrict__ ad1,
                                               const int* __restrict__ ew) {
    // ---- role: blockIdx.y == 4 -> edge histogram (overlapped with GEMM) ----
    if (blockIdx.y == 4) {
        __shared__ int s64;
        if (threadIdx.x == 0) {
            int is64 = 1;
#pragma unroll 1
            for (int k = 1; k < 129; k += 2)
                if (ew[k] != 0) { is64 = 0; break; }
            s64 = is64;
            if (blockIdx.x == 0) g_is64 = is64;
        }
        __syncthreads();
        int is64 = s64;
        const long long* ll = (const long long*)ew;
        int stride = GMX * 256;
        for (int i = blockIdx.x * 256 + threadIdx.x; i < ET; i += stride) {
            int d = (i < EE) ? (is64 ? (int)ll[EE + i] : ew[EE + i]) : (i - EE);
            atomicAdd(&g_deg[d], 1);
        }
        return;
    }

    __shared__ unsigned Ah[2][GM * ASTR];
    __shared__ unsigned Bh[2][GK * BSTR];
    __shared__ float s_es[GM], s_ed[GM];
    int tid = threadIdx.x;
    int bm = blockIdx.x * GM;
    int head = blockIdx.y;          // GN == dh == 64: one head per y-block
    int bn = head * GN;
    int wid = tid >> 5, lane = tid & 31;
    int wm = wid & 3, wn = wid >> 2;          // 4x2 warp grid, warp tile 32x32
    int g = lane >> 2, tg = lane & 3;

    // per-thread load coordinates (fixed across tiles)
    int ar0 = tid >> 2, akc0 = (tid & 3) * 4;          // A piece 0
    int ar1 = (tid + 256) >> 2, akc1 = ((tid + 256) & 3) * 4;  // A piece 1
    int bkk = tid >> 4, bnc = (tid & 15) * 4;

    float acc[2][4][4];
#pragma unroll
    for (int mi = 0; mi < 2; mi++)
#pragma unroll
        for (int ni = 0; ni < 4; ni++)
#pragma unroll
            for (int c = 0; c < 4; c++) acc[mi][ni][c] = 0.f;

    float4 a0v, a1v, bv;
    // fetch tile 0
    {
        a0v = make_float4(0.f, 0.f, 0.f, 0.f);
        a1v = make_float4(0.f, 0.f, 0.f, 0.f);
        if (bm + ar0 < NN) a0v = *(const float4*)&A[(size_t)(bm + ar0) * INF_ + akc0];
        if (bm + ar1 < NN) a1v = *(const float4*)&A[(size_t)(bm + ar1) * INF_ + akc1];
        bv = *(const float4*)&B[(size_t)bkk * CC + bn + bnc];
    }
    // store tile 0 -> buf 0
    {
        int base0 = ar0 * ASTR + akc0;
        Ah[0][base0] = tf32_of(a0v.x); Ah[0][base0 + 1] = tf32_of(a0v.y);
        Ah[0][base0 + 2] = tf32_of(a0v.z); Ah[0][base0 + 3] = tf32_of(a0v.w);
        int base1 = ar1 * ASTR + akc1;
        Ah[0][base1] = tf32_of(a1v.x); Ah[0][base1 + 1] = tf32_of(a1v.y);
        Ah[0][base1 + 2] = tf32_of(a1v.z); Ah[0][base1 + 3] = tf32_of(a1v.w);
        int bbase = bkk * BSTR + bnc;
        Bh[0][bbase] = tf32_of(bv.x); Bh[0][bbase + 1] = tf32_of(bv.y);
        Bh[0][bbase + 2] = tf32_of(bv.z); Bh[0][bbase + 3] = tf32_of(bv.w);
    }
    __syncthreads();

    int cur = 0;
#pragma unroll
    for (int kt = 0; kt < NKT; kt++) {
        // prefetch next tile into registers
        if (kt + 1 < NKT) {
            int k0 = (kt + 1) * GK;
            a0v = make_float4(0.f, 0.f, 0.f, 0.f);
            a1v = make_float4(0.f, 0.f, 0.f, 0.f);
            if (bm + ar0 < NN) a0v = *(const float4*)&A[(size_t)(bm + ar0) * INF_ + k0 + akc0];
            if (bm + ar1 < NN) a1v = *(const float4*)&A[(size_t)(bm + ar1) * INF_ + k0 + akc1];
            bv = *(const float4*)&B[(size_t)(k0 + bkk) * CC + bn + bnc];
        }
        // compute on buf[cur]
        const unsigned* Ac = Ah[cur];
        const unsigned* Bc = Bh[cur];
#pragma unroll
        for (int ks = 0; ks < 2; ks++) {
            int kb = ks * 8;
            unsigned ah[2][4];
#pragma unroll
            for (int mi = 0; mi < 2; mi++) {
                int R = wm * 32 + mi * 16;
                int b0 = (R + g) * ASTR + kb + tg;
                int b1 = (R + 8 + g) * ASTR + kb + tg;
                ah[mi][0] = Ac[b0]; ah[mi][1] = Ac[b1];
                ah[mi][2] = Ac[b0 + 4]; ah[mi][3] = Ac[b1 + 4];
            }
#pragma unroll
            for (int ni = 0; ni < 4; ni++) {
                int C = wn * 32 + ni * 8;
                unsigned bh0 = Bc[(kb + tg) * BSTR + C + g];
                unsigned bh1 = Bc[(kb + 4 + tg) * BSTR + C + g];
#pragma unroll
                for (int mi = 0; mi < 2; mi++)
                    mma_tf32(acc[mi][ni], ah[mi], bh0, bh1);
            }
        }
        // store prefetched tile into the other buffer
        if (kt + 1 < NKT) {
            int nxt = cur ^ 1;
            int base0 = ar0 * ASTR + akc0;
            Ah[nxt][base0] = tf32_of(a0v.x); Ah[nxt][base0 + 1] = tf32_of(a0v.y);
            Ah[nxt][base0 + 2] = tf32_of(a0v.z); Ah[nxt][base0 + 3] = tf32_of(a0v.w);
            int base1 = ar1 * ASTR + akc1;
            Ah[nxt][base1] = tf32_of(a1v.x); Ah[nxt][base1 + 1] = tf32_of(a1v.y);
            Ah[nxt][base1 + 2] = tf32_of(a1v.z); Ah[nxt][base1 + 3] = tf32_of(a1v.w);
            int bbase = bkk * BSTR + bnc;
            Bh[nxt][bbase] = tf32_of(bv.x); Bh[nxt][bbase + 1] = tf32_of(bv.y);
            Bh[nxt][bbase + 2] = tf32_of(bv.z); Bh[nxt][bbase + 3] = tf32_of(bv.w);
            __syncthreads();
            cur = nxt;
        }
    }

    // epilogue 1: fp16 h1 store
#pragma unroll
    for (int mi = 0; mi < 2; mi++) {
        int row0 = bm + wm * 32 + mi * 16 + g;
#pragma unroll
        for (int ni = 0; ni < 4; ni++) {
            int col = bn + wn * 32 + ni * 8 + 2 * tg;   // even
            if (row0 < NN)
                g_h1h[(size_t)row0 * (CC / 2) + (col >> 1)] =
                    h2bits(acc[mi][ni][0], acc[mi][ni][1]);
            if (row0 + 8 < NN)
                g_h1h[(size_t)(row0 + 8) * (CC / 2) + (col >> 1)] =
                    h2bits(acc[mi][ni][2], acc[mi][ni][3]);
        }
    }

    // epilogue 2: per-row es/ed dot over this head's 64 channels
    const float* asv = as1 + head * GN;
    const float* adv = ad1 + head * GN;
    float ps[2][2] = {{0, 0}, {0, 0}};   // [mi][row0 / row0+8]
    float pd[2][2] = {{0, 0}, {0, 0}};
#pragma unroll
    for (int ni = 0; ni < 4; ni++) {
        int c = wn * 32 + ni * 8 + 2 * tg;   // local col within head
        float a0 = asv[c], a1 = asv[c + 1];
        float d0 = adv[c], d1 = adv[c + 1];
#pragma unroll
        for (int mi = 0; mi < 2; mi++) {
            ps[mi][0] += acc[mi][ni][0] * a0 + acc[mi][ni][1] * a1;
            pd[mi][0] += acc[mi][ni][0] * d0 + acc[mi][ni][1] * d1;
            ps[mi][1] += acc[mi][ni][2] * a0 + acc[mi][ni][3] * a1;
            pd[mi][1] += acc[mi][ni][2] * d0 + acc[mi][ni][3] * d1;
        }
    }
#pragma unroll
    for (int off = 1; off <= 2; off <<= 1) {
#pragma unroll
        for (int mi = 0; mi < 2; mi++)
#pragma unroll
            for (int rr = 0; rr < 2; rr++) {
                ps[mi][rr] += __shfl_xor_sync(0xffffffffu, ps[mi][rr], off);
                pd[mi][rr] += __shfl_xor_sync(0xffffffffu, pd[mi][rr], off);
            }
    }
    if (wn == 1 && tg == 0) {
#pragma unroll
        for (int mi = 0; mi < 2; mi++)
#pragma unroll
            for (int rr = 0; rr < 2; rr++) {
                int R = wm * 32 + mi * 16 + rr * 8 + g;
                s_es[R] = ps[mi][rr];
                s_ed[R] = pd[mi][rr];
            }
    }
    __syncthreads();
    if (wn == 0 && tg == 0) {
#pragma unroll
        for (int mi = 0; mi < 2; mi++)
#pragma unroll
            for (int rr = 0; rr < 2; rr++) {
                int R = wm * 32 + mi * 16 + rr * 8 + g;
                int row = bm + R;
                if (row < NN) {
                    ((float*)&g_es1[row])[head] = ps[mi][rr] + s_es[R];
                    ((float*)&g_ed1[row])[head] = pd[mi][rr] + s_ed[R];
                }
            }
    }
}

// ------- layer-1 softmax + aggregation (warp per node; x4 unroll) -----------
__device__ __forceinline__ void agg_edge(float4 ev, uint4 hv, float4 edn, int lane,
                                         float* acc, float& d0, float& d1,
                                         float& d2, float& d3) {
    float p0 = __expf(lrelu(ev.x + edn.x));
    float p1 = __expf(lrelu(ev.y + edn.y));
    float p2 = __expf(lrelu(ev.z + edn.z));
    float p3 = __expf(lrelu(ev.w + edn.w));
    d0 += p0; d1 += p1; d2 += p2; d3 += p3;
    float pv = lane < 8 ? p0 : lane < 16 ? p1 : lane < 24 ? p2 : p3;
    float e0, e1, e2, e3, e4, e5, e6, e7;
    bits2f(hv.x, e0, e1); bits2f(hv.y, e2, e3);
    bits2f(hv.z, e4, e5); bits2f(hv.w, e6, e7);
    acc[0] = fmaf(pv, e0, acc[0]); acc[1] = fmaf(pv, e1, acc[1]);
    acc[2] = fmaf(pv, e2, acc[2]); acc[3] = fmaf(pv, e3, acc[3]);
    acc[4] = fmaf(pv, e4, acc[4]); acc[5] = fmaf(pv, e5, acc[5]);
    acc[6] = fmaf(pv, e6, acc[6]); acc[7] = fmaf(pv, e7, acc[7]);
}

__global__ __launch_bounds__(256) void k_agg1() {
    __shared__ float bnP[2][8][CC];   // [sum/sq][warp][channel], 16KB
    int tid = threadIdx.x;
    int wid = tid >> 5;
    int lane = tid & 31;
    int n = (blockIdx.x << 3) + wid;  // NN = 6250 blocks * 8 warps exactly
    int r0 = g_rowptr[n], r1 = g_rowptr[n + 1];
    float4 edn = g_ed1[n];
    float acc[8] = {0, 0, 0, 0, 0, 0, 0, 0};
    float d0 = 0.f, d1 = 0.f, d2 = 0.f, d3 = 0.f;
    int j = r0;
    for (; j + 3 < r1; j += 4) {
        int s0 = g_sed[j].x, s1 = g_sed[j + 1].x, s2 = g_sed[j + 2].x, s3 = g_sed[j + 3].x;
        float4 e0 = g_es1[s0], e1 = g_es1[s1], e2 = g_es1[s2], e3 = g_es1[s3];
        uint4 h0 = ((const uint4*)(g_h1h + (size_t)s0 * (CC / 2)))[lane];
        uint4 h1 = ((const uint4*)(g_h1h + (size_t)s1 * (CC / 2)))[lane];
        uint4 h2 = ((const uint4*)(g_h1h + (size_t)s2 * (CC / 2)))[lane];
        uint4 h3 = ((const uint4*)(g_h1h + (size_t)s3 * (CC / 2)))[lane];
        agg_edge(e0, h0, edn, lane, acc, d0, d1, d2, d3);
        agg_edge(e1, h1, edn, lane, acc, d0, d1, d2, d3);
        agg_edge(e2, h2, edn, lane, acc, d0, d1, d2, d3);
        agg_edge(e3, h3, edn, lane, acc, d0, d1, d2, d3);
    }
    for (; j < r1; j++) {
        int s0 = g_sed[j].x;
        float4 e0 = g_es1[s0];
        uint4 h0 = ((const uint4*)(g_h1h + (size_t)s0 * (CC / 2)))[lane];
        agg_edge(e0, h0, edn, lane, acc, d0, d1, d2, d3);
    }
    // d0..d3 already complete in every lane: NO cross-lane reduction.
    float inv0 = 1.f / (d0 + 1e-16f);
    float inv1 = 1.f / (d1 + 1e-16f);
    float inv2 = 1.f / (d2 + 1e-16f);
    float inv3 = 1.f / (d3 + 1e-16f);
    float invv = lane < 8 ? inv0 : lane < 16 ? inv1 : lane < 24 ? inv2 : inv3;
    float o[8];
#pragma unroll
    for (int i = 0; i < 8; i++) o[i] = acc[i] * invv;
    float4* orow = (float4*)&g_out1[(size_t)n * CC];
    orow[2 * lane]     = make_float4(o[0], o[1], o[2], o[3]);
    orow[2 * lane + 1] = make_float4(o[4], o[5], o[6], o[7]);
    // conflict-free BN partials: contiguous float4 stores per lane
    {
        float4* ds = (float4*)&bnP[0][wid][8 * lane];
        ds[0] = make_float4(o[0], o[1], o[2], o[3]);
        ds[1] = make_float4(o[4], o[5], o[6], o[7]);
        float4* dq = (float4*)&bnP[1][wid][8 * lane];
        dq[0] = make_float4(o[0] * o[0], o[1] * o[1], o[2] * o[2], o[3] * o[3]);
        dq[1] = make_float4(o[4] * o[4], o[5] * o[5], o[6] * o[6], o[7] * o[7]);
    }
    __syncthreads();
    float s = 0.f, q = 0.f;
#pragma unroll
    for (int w = 0; w < 8; w++) {
        s += bnP[0][w][tid];
        q += bnP[1][w][tid];
    }
    atomicAdd(&g_bnsum[tid], s);
    atomicAdd(&g_bnsq[tid], q);
}

// --- fused BN-finalize + BN-apply + ELU + GEMM2 + layer-2 logits ------------
__global__ __launch_bounds__(256) void k_l2pre(const float* __restrict__ gamma,
                                               const float* __restrict__ beta,
                                               const float* __restrict__ W2,
                                               const float* __restrict__ as2,
                                               const float* __restrict__ ad2) {
    __shared__ float s_sc[CC], s_sh[CC];
    int tid = threadIdx.x;
    {
        float mean = g_bnsum[tid] * (1.f / NN);
        float var = g_bnsq[tid] * (1.f / NN) - mean * mean;
        if (var < 0.f) var = 0.f;
        float sc = gamma[tid] * rsqrtf(var + 1e-5f);
        s_sc[tid] = sc;
        s_sh[tid] = beta[tid] - mean * sc;
    }
    __syncthreads();
    int n = (blockIdx.x << 3) + (tid >> 5);
    int lane = tid & 31;
    const float4* orow = (const float4*)&g_out1[(size_t)n * CC];
    const float4* sc4 = (const float4*)s_sc;
    const float4* sh4 = (const float4*)s_sh;
    const float2* W2v = (const float2*)W2;   // [256] of (w0,w1)
    float a0 = 0.f, a1 = 0.f;
#pragma unroll
    for (int half = 0; half < 2; half++) {
        int idx = half * 32 + lane;
        float4 ov = orow[idx];
        float4 sc = sc4[idx];
        float4 sh = sh4[idx];
        float v[4] = {ov.x * sc.x + sh.x, ov.y * sc.y + sh.y,
                      ov.z * sc.z + sh.z, ov.w * sc.w + sh.w};
#pragma unroll
        for (int i = 0; i < 4; i++) {
            float vv = v[i] > 0.f ? v[i] : expm1f(v[i]);
            float2 w = W2v[idx * 4 + i];
            a0 = fmaf(vv, w.x, a0);
            a1 = fmaf(vv, w.y, a1);
        }
    }
#pragma unroll
    for (int off = 16; off; off >>= 1) {
        a0 += __shfl_xor_sync(0xffffffffu, a0, off);
        a1 += __shfl_xor_sync(0xffffffffu, a1, off);
    }
    if (lane == 0) {
        g_h2[n] = make_float2(a0, a1);
        g_es2[n] = a0 * as2[0] + a1 * as2[1];
        g_ed2[n] = a0 * ad2[0] + a1 * ad2[1];
    }
}

// --- layer-2 softmax + aggregation + att output + scratch re-zero -----------
__global__ void k_agg2(const float* __restrict__ bias2, float* __restrict__ out) {
    // re-zero scratch for the NEXT graph replay (independent addresses)
    {
        int gid = blockIdx.x * 256 + threadIdx.x;
        if (gid < NN) { g_deg[gid] = 0; g_cnt[gid] = 0; }
        if (gid < CC) { g_bnsum[gid] = 0.f; g_bnsq[gid] = 0.f; }
    }
    int n = (blockIdx.x * 256 + threadIdx.x) >> 5;
    int lane = threadIdx.x & 31;
    if (n >= NN) return;
    int r0 = g_rowptr[n], r1 = g_rowptr[n + 1];
    float edn = g_ed2[n];
    float den = 0.f, a0 = 0.f, a1 = 0.f;
    for (int j = r0 + lane; j < r1; j += 32) {
        int s = g_sed[j].x;
        float p = __expf(lrelu(g_es2[s] + edn));
        den += p;
        float2 h = g_h2[s];
        a0 = fmaf(p, h.x, a0);
        a1 = fmaf(p, h.y, a1);
    }
#pragma unroll
    for (int off = 16; off; off >>= 1) {
        den += __shfl_xor_sync(0xffffffffu, den, off);
        a0  += __shfl_xor_sync(0xffffffffu, a0, off);
        a1  += __shfl_xor_sync(0xffffffffu, a1, off);
    }
    float inv = 1.f / (den + 1e-16f);
    for (int j = r0 + lane; j < r1; j += 32) {
        int2 se = g_sed[j];
        float p = __expf(lrelu(g_es2[se.x] + edn));
        out[2 * NN + se.y] = p * inv;
    }
    if (lane == 0) {
        out[2 * n]     = a0 * inv + bias2[0];
        out[2 * n + 1] = a1 * inv + bias2[1];
    }
}

// ---------------- launch (single stream) ----------------
extern "C" void kernel_launch(void* const* d_in, const int* in_sizes, int n_in,
                              void* d_out, int out_size) {
    const float* x     = (const float*)d_in[0];
    const int*   ei    = (const int*)d_in[1];     // int32 or int64, autodetected
    const float* W1    = (const float*)d_in[2];
    const float* as1   = (const float*)d_in[3];
    const float* ad1   = (const float*)d_in[4];
    // d_in[5] = bias1 (cancels under batch-norm; skipped)
    const float* gamma = (const float*)d_in[6];
    const float* beta  = (const float*)d_in[7];
    const float* W2    = (const float*)d_in[8];
    const float* as2   = (const float*)d_in[9];
    const float* ad2   = (const float*)d_in[10];
    const float* bias2 = (const float*)d_in[11];
    float*       out   = (float*)d_out;

    // GEMM1 + es/ed epilogue + HIST role (y==4) in one launch
    dim3 ggrid(GMX, 5);
    k_gemm1<<<ggrid, 256>>>(x, W1, as1, ad1, ei);

    // CSR scans + scatter (deg produced by gemm1's hist role)
    k_scan1<<<NSCAN_BLK, 256>>>();
    k_scan3<<<NSCAN_BLK, 256>>>();
    k_scatter<<<(ET + 511) / 512, 256>>>(ei);

    int wgrid = (NN + 7) / 8;  // 8 warps per 256-thread block
    k_agg1<<<wgrid, 256>>>();

    // layer 2 (BN finalize fused into l2pre)
    k_l2pre<<<wgrid, 256>>>(gamma, beta, W2, as2, ad2);
    k_agg2<<<wgrid, 256>>>(bias2, out);
}